// round 1
// baseline (speedup 1.0000x reference)
#include <cuda_runtime.h>
#include <math.h>

#define B_ 256
#define T_ 256
#define V_ 128
#define D_ 384
#define H_ 6
#define HS_ 64
#define L_ 6
#define FF_ 1536
#define N_ (B_*T_)   // 65536 tokens

// ---------------- scratch (allocation-free rule: __device__ globals) -------
__device__ float g_x [N_*D_];
__device__ float g_xn[N_*D_];
__device__ float g_q [N_*D_];
__device__ float g_k [N_*D_];
__device__ float g_v [N_*D_];
__device__ float g_o [N_*D_];
__device__ float g_h [N_*FF_];

// ---------------- embedding ------------------------------------------------
__global__ void embed_kernel(const int* __restrict__ idx,
                             const float* __restrict__ tok,
                             const float* __restrict__ pos,
                             float* __restrict__ x) {
    int i = blockIdx.x * 256 + threadIdx.x;   // over N_*D_/4 float4s
    int n = i / (D_/4);
    int dq = i % (D_/4);
    int t = n & (T_-1);
    int id = idx[n];
    float4 a = ((const float4*)tok)[id * (D_/4) + dq];
    float4 p = ((const float4*)pos)[t  * (D_/4) + dq];
    float4 r;
    r.x = a.x + p.x; r.y = a.y + p.y; r.z = a.z + p.z; r.w = a.w + p.w;
    ((float4*)x)[i] = r;
}

// ---------------- layernorm (warp per row) ---------------------------------
__global__ void ln_kernel(const float* __restrict__ x,
                          const float* __restrict__ g,
                          const float* __restrict__ b,
                          float* __restrict__ out) {
    int row  = blockIdx.x * 8 + (threadIdx.x >> 5);
    int lane = threadIdx.x & 31;
    const float* xr = x + (size_t)row * D_;
    float vals[12];
    float s = 0.f, s2 = 0.f;
#pragma unroll
    for (int i = 0; i < 12; i++) {
        float t = xr[lane + 32*i];
        vals[i] = t; s += t; s2 += t*t;
    }
#pragma unroll
    for (int off = 16; off; off >>= 1) {
        s  += __shfl_xor_sync(0xffffffffu, s,  off);
        s2 += __shfl_xor_sync(0xffffffffu, s2, off);
    }
    float mean = s * (1.f/D_);
    float var  = s2 * (1.f/D_) - mean*mean;
    float rstd = rsqrtf(var + 1e-5f);
    float* orow = out + (size_t)row * D_;
#pragma unroll
    for (int i = 0; i < 12; i++) {
        int d = lane + 32*i;
        orow[d] = (vals[i] - mean) * rstd * g[d] + b[d];
    }
}

// ---------------- SGEMM: C[N x M] = A[N x K] @ B[K x M] (+epilogue) --------
// MODE: 0 none, 1 +bias, 2 relu(+bias), 3 +bias+residual
// HEADOUT: M=64, B selected per blockIdx.z head, C written [B,H,T,HS]
template<int MODE, bool HEADOUT>
__global__ __launch_bounds__(256)
void gemm_kernel(const float* __restrict__ A, const float* __restrict__ Bw,
                 const float* __restrict__ bias, const float* __restrict__ res,
                 float* __restrict__ C, int K, int M) {
    __shared__ float As[16][132];   // transposed A tile [k][row], +4 pad
    __shared__ float Bs[16][64];    // B tile [k][col]
    const int tid = threadIdx.x;
    const int tx = tid & 15, ty = tid >> 4;
    const int r0 = blockIdx.y * 128;
    const int n0 = HEADOUT ? 0 : blockIdx.x * 64;
    const int ldb = HEADOUT ? 64 : M;
    const float* Bp = Bw + (HEADOUT ? (size_t)blockIdx.z * (size_t)K * 64 : (size_t)0);

    float acc[8][4];
#pragma unroll
    for (int i = 0; i < 8; i++)
#pragma unroll
        for (int j = 0; j < 4; j++) acc[i][j] = 0.f;

    const int kk = tid >> 4, c4 = tid & 15;     // B-load mapping
    for (int k0 = 0; k0 < K; k0 += 16) {
#pragma unroll
        for (int i = 0; i < 2; i++) {           // A tile: 512 float4s / 256 thr
            int f = tid + 256*i;
            int row = f >> 2, kq = f & 3;
            float4 av = *(const float4*)(A + (size_t)(r0+row)*K + k0 + kq*4);
            As[kq*4+0][row] = av.x; As[kq*4+1][row] = av.y;
            As[kq*4+2][row] = av.z; As[kq*4+3][row] = av.w;
        }
        *(float4*)&Bs[kk][c4*4] =
            *(const float4*)(Bp + (size_t)(k0+kk)*ldb + n0 + c4*4);
        __syncthreads();
#pragma unroll
        for (int k = 0; k < 16; k++) {
            float4 a0 = *(float4*)&As[k][ty*8];
            float4 a1 = *(float4*)&As[k][ty*8+4];
            float4 bv = *(float4*)&Bs[k][tx*4];
            float ar[8] = {a0.x,a0.y,a0.z,a0.w,a1.x,a1.y,a1.z,a1.w};
            float br[4] = {bv.x,bv.y,bv.z,bv.w};
#pragma unroll
            for (int i = 0; i < 8; i++)
#pragma unroll
                for (int j = 0; j < 4; j++)
                    acc[i][j] += ar[i]*br[j];
        }
        __syncthreads();
    }

    float4 bv4 = make_float4(0.f,0.f,0.f,0.f);
    if (MODE >= 1) {
        bv4.x = bias[n0+tx*4+0]; bv4.y = bias[n0+tx*4+1];
        bv4.z = bias[n0+tx*4+2]; bv4.w = bias[n0+tx*4+3];
    }
#pragma unroll
    for (int i = 0; i < 8; i++) {
        int rr = r0 + ty*8 + i;
        float4 o = make_float4(acc[i][0]+bv4.x, acc[i][1]+bv4.y,
                               acc[i][2]+bv4.z, acc[i][3]+bv4.w);
        if (MODE == 2) {
            o.x = fmaxf(o.x, 0.f); o.y = fmaxf(o.y, 0.f);
            o.z = fmaxf(o.z, 0.f); o.w = fmaxf(o.w, 0.f);
        }
        if (HEADOUT) {
            int bb = rr >> 8, t = rr & 255;
            size_t oi = (((size_t)bb*H_ + blockIdx.z)*T_ + t)*64 + tx*4;
            *(float4*)(C + oi) = o;
        } else {
            size_t ci = (size_t)rr*M + n0 + tx*4;
            if (MODE == 3) {
                float4 rv = *(const float4*)(res + ci);
                o.x += rv.x; o.y += rv.y; o.z += rv.z; o.w += rv.w;
            }
            *(float4*)(C + ci) = o;
        }
    }
}

// ---------------- causal flash attention -----------------------------------
// q,k,v layout [B,H,T,HS]; o written [B,T,H*HS] (heads concatenated)
__global__ __launch_bounds__(256)
void attn_kernel(const float* __restrict__ q, const float* __restrict__ k,
                 const float* __restrict__ v, float* __restrict__ o) {
    extern __shared__ float sm[];
    float* Qs  = sm;            // [64][68] transposed: Qs[d][r]
    float* KPs = sm + 64*68;    // Ks[d][c], reused as Ps[r][c]
    float* Vs  = sm + 2*64*68;  // Vs[s][d]
    const int tid = threadIdx.x;
    const int tx = tid & 15, ty = tid >> 4;
    const int bh = blockIdx.y;
    const int q0 = blockIdx.x * 64;
    const float* qb = q + (size_t)bh*T_*64;
    const float* kb = k + (size_t)bh*T_*64;
    const float* vb = v + (size_t)bh*T_*64;

#pragma unroll
    for (int i = 0; i < 16; i++) {
        int e = tid + 256*i;
        int r = e >> 6, d = e & 63;
        Qs[d*68 + r] = qb[(q0+r)*64 + d];
    }

    const float NEG = -1e30f;
    float m[4], lse[4], acc[4][4];
#pragma unroll
    for (int i = 0; i < 4; i++) {
        m[i] = NEG; lse[i] = 0.f;
#pragma unroll
        for (int j = 0; j < 4; j++) acc[i][j] = 0.f;
    }
    const float scale = 0.125f;   // 64^-0.5

    for (int s0 = 0; s0 <= q0; s0 += 64) {
        __syncthreads();
#pragma unroll
        for (int i = 0; i < 16; i++) {
            int e = tid + 256*i;
            int r = e >> 6, d = e & 63;
            KPs[d*68 + r] = kb[(s0+r)*64 + d];
            Vs [r*68 + d] = vb[(s0+r)*64 + d];
        }
        __syncthreads();

        float s[4][4];
#pragma unroll
        for (int i = 0; i < 4; i++)
#pragma unroll
            for (int j = 0; j < 4; j++) s[i][j] = 0.f;
#pragma unroll 16
        for (int d = 0; d < 64; d++) {
            float4 a = *(float4*)&Qs [d*68 + ty*4];
            float4 b = *(float4*)&KPs[d*68 + tx*4];
            float ar[4] = {a.x,a.y,a.z,a.w};
            float br[4] = {b.x,b.y,b.z,b.w};
#pragma unroll
            for (int i = 0; i < 4; i++)
#pragma unroll
                for (int j = 0; j < 4; j++)
                    s[i][j] += ar[i]*br[j];
        }

#pragma unroll
        for (int i = 0; i < 4; i++) {
            int row = q0 + ty*4 + i;
            float tm = NEG;
#pragma unroll
            for (int j = 0; j < 4; j++) {
                int col = s0 + tx*4 + j;
                float val = (col <= row) ? s[i][j]*scale : NEG;
                s[i][j] = val;
                tm = fmaxf(tm, val);
            }
            tm = fmaxf(tm, __shfl_xor_sync(0xffffffffu, tm, 1));
            tm = fmaxf(tm, __shfl_xor_sync(0xffffffffu, tm, 2));
            tm = fmaxf(tm, __shfl_xor_sync(0xffffffffu, tm, 4));
            tm = fmaxf(tm, __shfl_xor_sync(0xffffffffu, tm, 8));
            float nm = fmaxf(m[i], tm);
            float corr = __expf(m[i] - nm);
            m[i] = nm;
            float rs = 0.f;
#pragma unroll
            for (int j = 0; j < 4; j++) {
                float p = __expf(s[i][j] - nm);
                s[i][j] = p;
                rs += p;
            }
            rs += __shfl_xor_sync(0xffffffffu, rs, 1);
            rs += __shfl_xor_sync(0xffffffffu, rs, 2);
            rs += __shfl_xor_sync(0xffffffffu, rs, 4);
            rs += __shfl_xor_sync(0xffffffffu, rs, 8);
            lse[i] = lse[i]*corr + rs;
#pragma unroll
            for (int j = 0; j < 4; j++) acc[i][j] *= corr;
        }

        __syncthreads();          // done reading K tile
#pragma unroll
        for (int i = 0; i < 4; i++)
            *(float4*)&KPs[(ty*4+i)*68 + tx*4] =
                make_float4(s[i][0], s[i][1], s[i][2], s[i][3]);
        __syncthreads();

#pragma unroll 16
        for (int sI = 0; sI < 64; sI++) {
            float4 vv = *(float4*)&Vs[sI*68 + tx*4];
            float vr[4] = {vv.x,vv.y,vv.z,vv.w};
            float pr[4];
#pragma unroll
            for (int i = 0; i < 4; i++) pr[i] = KPs[(ty*4+i)*68 + sI];
#pragma unroll
            for (int i = 0; i < 4; i++)
#pragma unroll
                for (int j = 0; j < 4; j++)
                    acc[i][j] += pr[i]*vr[j];
        }
    }

    int bb = bh / H_, h = bh % H_;
#pragma unroll
    for (int i = 0; i < 4; i++) {
        float inv = 1.f / lse[i];
        int t = q0 + ty*4 + i;
        size_t oi = ((size_t)bb*T_ + t)*D_ + h*64 + tx*4;
        *(float4*)(o + oi) = make_float4(acc[i][0]*inv, acc[i][1]*inv,
                                         acc[i][2]*inv, acc[i][3]*inv);
    }
}

// ---------------- launch ----------------------------------------------------
extern "C" void kernel_launch(void* const* d_in, const int* in_sizes, int n_in,
                              void* d_out, int out_size) {
    const int*   idx   = (const int*)  d_in[0];
    const float* tok   = (const float*)d_in[1];
    const float* pos   = (const float*)d_in[2];
    const float* Wq    = (const float*)d_in[3];
    const float* Wk    = (const float*)d_in[4];
    const float* Wv    = (const float*)d_in[5];
    const float* Wproj = (const float*)d_in[6];
    const float* bproj = (const float*)d_in[7];
    const float* ln1g  = (const float*)d_in[8];
    const float* ln1b  = (const float*)d_in[9];
    const float* ln2g  = (const float*)d_in[10];
    const float* ln2b  = (const float*)d_in[11];
    const float* W1    = (const float*)d_in[12];
    const float* b1    = (const float*)d_in[13];
    const float* W2    = (const float*)d_in[14];
    const float* b2    = (const float*)d_in[15];
    const float* lnfg  = (const float*)d_in[16];
    const float* lnfb  = (const float*)d_in[17];
    const float* Wlm   = (const float*)d_in[18];
    const float* blm   = (const float*)d_in[19];
    float* out = (float*)d_out;

    float *x, *xn, *q, *k, *v, *o, *h;
    cudaGetSymbolAddress((void**)&x,  g_x);
    cudaGetSymbolAddress((void**)&xn, g_xn);
    cudaGetSymbolAddress((void**)&q,  g_q);
    cudaGetSymbolAddress((void**)&k,  g_k);
    cudaGetSymbolAddress((void**)&v,  g_v);
    cudaGetSymbolAddress((void**)&o,  g_o);
    cudaGetSymbolAddress((void**)&h,  g_h);

    cudaFuncSetAttribute(attn_kernel,
        cudaFuncAttributeMaxDynamicSharedMemorySize, 3*64*68*4);

    embed_kernel<<<(N_*D_/4)/256, 256>>>(idx, tok, pos, x);

    for (int l = 0; l < L_; l++) {
        ln_kernel<<<N_/8, 256>>>(x, ln1g + l*D_, ln1b + l*D_, xn);

        dim3 gq(1, N_/128, H_);
        size_t woff = (size_t)l * H_ * D_ * HS_;
        gemm_kernel<0,true><<<gq, 256>>>(xn, Wq + woff, nullptr, nullptr, q, D_, 64);
        gemm_kernel<0,true><<<gq, 256>>>(xn, Wk + woff, nullptr, nullptr, k, D_, 64);
        gemm_kernel<0,true><<<gq, 256>>>(xn, Wv + woff, nullptr, nullptr, v, D_, 64);

        attn_kernel<<<dim3(T_/64, B_*H_), 256, 3*64*68*4>>>(q, k, v, o);

        gemm_kernel<3,false><<<dim3(D_/64, N_/128), 256>>>(
            o, Wproj + (size_t)l*D_*D_, bproj + l*D_, x, x, D_, D_);

        ln_kernel<<<N_/8, 256>>>(x, ln2g + l*D_, ln2b + l*D_, xn);

        gemm_kernel<2,false><<<dim3(FF_/64, N_/128), 256>>>(
            xn, W1 + (size_t)l*D_*FF_, b1 + l*FF_, nullptr, h, D_, FF_);

        gemm_kernel<3,false><<<dim3(D_/64, N_/128), 256>>>(
            h, W2 + (size_t)l*FF_*D_, b2 + l*D_, x, x, FF_, D_);
    }

    ln_kernel<<<N_/8, 256>>>(x, lnfg, lnfb, xn);
    gemm_kernel<1,false><<<dim3(V_/64, N_/128), 256>>>(
        xn, Wlm, blm, nullptr, out, D_, V_);
}

// round 4
// speedup vs baseline: 1.4984x; 1.4984x over previous
#include <cuda_runtime.h>
#include <cstdint>
#include <math.h>

#define B_ 256
#define T_ 256
#define V_ 128
#define D_ 384
#define H_ 6
#define HS_ 64
#define L_ 6
#define FF_ 1536
#define N_ (B_*T_)   // 65536 tokens

// ---------------- scratch (allocation-free rule: __device__ globals) -------
__device__ float g_x [N_*D_];
__device__ float g_xn[N_*D_];
__device__ float g_q [N_*D_];
__device__ float g_k [N_*D_];
__device__ float g_v [N_*D_];
__device__ float g_o [N_*D_];
__device__ float g_h [N_*FF_];

// ---------------- embedding ------------------------------------------------
__global__ void embed_kernel(const int* __restrict__ idx,
                             const float* __restrict__ tok,
                             const float* __restrict__ pos,
                             float* __restrict__ x) {
    int i = blockIdx.x * 256 + threadIdx.x;
    int n = i / (D_/4);
    int dq = i % (D_/4);
    int t = n & (T_-1);
    int id = idx[n];
    float4 a = ((const float4*)tok)[id * (D_/4) + dq];
    float4 p = ((const float4*)pos)[t  * (D_/4) + dq];
    float4 r;
    r.x = a.x + p.x; r.y = a.y + p.y; r.z = a.z + p.z; r.w = a.w + p.w;
    ((float4*)x)[i] = r;
}

// ---------------- layernorm (warp per row) ---------------------------------
__global__ void ln_kernel(const float* __restrict__ x,
                          const float* __restrict__ g,
                          const float* __restrict__ b,
                          float* __restrict__ out) {
    int row  = blockIdx.x * 8 + (threadIdx.x >> 5);
    int lane = threadIdx.x & 31;
    const float* xr = x + (size_t)row * D_;
    float vals[12];
    float s = 0.f, s2 = 0.f;
#pragma unroll
    for (int i = 0; i < 12; i++) {
        float t = xr[lane + 32*i];
        vals[i] = t; s += t; s2 += t*t;
    }
#pragma unroll
    for (int off = 16; off; off >>= 1) {
        s  += __shfl_xor_sync(0xffffffffu, s,  off);
        s2 += __shfl_xor_sync(0xffffffffu, s2, off);
    }
    float mean = s * (1.f/D_);
    float var  = s2 * (1.f/D_) - mean*mean;
    float rstd = rsqrtf(var + 1e-5f);
    float* orow = out + (size_t)row * D_;
#pragma unroll
    for (int i = 0; i < 12; i++) {
        int d = lane + 32*i;
        orow[d] = (vals[i] - mean) * rstd * g[d] + b[d];
    }
}

// ---------------- TF32 helpers ---------------------------------------------
__device__ __forceinline__ uint32_t f2tf32(float f) {
    uint32_t r;
    asm("cvt.rna.tf32.f32 %0, %1;" : "=r"(r) : "f"(f));
    return r;
}

__device__ __forceinline__ void mma_tf32(float c[4], const uint32_t a[4],
                                         const uint32_t b[2]) {
    asm volatile(
        "mma.sync.aligned.m16n8k8.row.col.f32.tf32.tf32.f32 "
        "{%0,%1,%2,%3}, {%4,%5,%6,%7}, {%8,%9}, {%0,%1,%2,%3};"
        : "+f"(c[0]), "+f"(c[1]), "+f"(c[2]), "+f"(c[3])
        : "r"(a[0]), "r"(a[1]), "r"(a[2]), "r"(a[3]),
          "r"(b[0]), "r"(b[1]));
}

// ---------------- TF32 tensor-core GEMM ------------------------------------
// C[N x M] = A[N x K] @ B[K x M] (+epilogue)
// MODE: 0 none, 1 +bias, 2 relu(+bias), 3 +bias+residual
// HEADOUT: M=64, B selected per blockIdx.z head, C written [B,H,T,HS]
// CTA tile 128x64, BK=32, 8 warps each 32x32 (warp grid 4x2).
template<int MODE, bool HEADOUT>
__global__ __launch_bounds__(256)
void gemm_tc(const float* __restrict__ A, const float* __restrict__ Bw,
             const float* __restrict__ bias, const float* __restrict__ res,
             float* __restrict__ C, int K, int M) {
    __shared__ uint32_t As[32][132];   // [k][m] tf32
    __shared__ uint32_t Bs[32][68];    // [k][n] tf32
    const int tid  = threadIdx.x;
    const int lane = tid & 31, warp = tid >> 5;
    const int gid  = lane >> 2, tig = lane & 3;
    const int wm   = warp >> 1, wn = warp & 1;     // warp tile origin
    const int m0   = wm * 32,   n0w = wn * 32;
    const int r0   = blockIdx.y * 128;
    const int n0   = HEADOUT ? 0 : blockIdx.x * 64;
    const int ldb  = HEADOUT ? 64 : M;
    const float* Bp = Bw + (HEADOUT ? (size_t)blockIdx.z * (size_t)K * 64
                                    : (size_t)0);

    float acc[2][4][4];
#pragma unroll
    for (int i = 0; i < 2; i++)
#pragma unroll
        for (int j = 0; j < 4; j++)
#pragma unroll
            for (int c = 0; c < 4; c++) acc[i][j][c] = 0.f;

    for (int k0 = 0; k0 < K; k0 += 32) {
        // A tile: 128x32 floats = 1024 float4 over 256 threads
#pragma unroll
        for (int i = 0; i < 4; i++) {
            int f = i*256 + tid;
            int row = f >> 3, kq = f & 7;
            float4 av = *(const float4*)(A + (size_t)(r0+row)*K + k0 + kq*4);
            As[kq*4+0][row] = f2tf32(av.x);
            As[kq*4+1][row] = f2tf32(av.y);
            As[kq*4+2][row] = f2tf32(av.z);
            As[kq*4+3][row] = f2tf32(av.w);
        }
        // B tile: 32x64 floats = 512 float4 over 256 threads
#pragma unroll
        for (int i = 0; i < 2; i++) {
            int f = i*256 + tid;
            int kk = f >> 4, c4 = f & 15;
            float4 bv = *(const float4*)(Bp + (size_t)(k0+kk)*ldb + n0 + c4*4);
            uint4 tv;
            tv.x = f2tf32(bv.x); tv.y = f2tf32(bv.y);
            tv.z = f2tf32(bv.z); tv.w = f2tf32(bv.w);
            *(uint4*)&Bs[kk][c4*4] = tv;
        }
        __syncthreads();

#pragma unroll
        for (int ks = 0; ks < 4; ks++) {
            const int kb = ks * 8;
            uint32_t af[2][4], bf[4][2];
#pragma unroll
            for (int mi = 0; mi < 2; mi++) {
                int rb = m0 + mi*16 + gid;
                af[mi][0] = As[kb + tig    ][rb];
                af[mi][1] = As[kb + tig    ][rb + 8];
                af[mi][2] = As[kb + tig + 4][rb];
                af[mi][3] = As[kb + tig + 4][rb + 8];
            }
#pragma unroll
            for (int ni = 0; ni < 4; ni++) {
                int cb = n0w + ni*8 + gid;
                bf[ni][0] = Bs[kb + tig    ][cb];
                bf[ni][1] = Bs[kb + tig + 4][cb];
            }
#pragma unroll
            for (int mi = 0; mi < 2; mi++)
#pragma unroll
                for (int ni = 0; ni < 4; ni++)
                    mma_tf32(acc[mi][ni], af[mi], bf[ni]);
        }
        __syncthreads();
    }

    // epilogue: c0/c1 at (row, col..col+1), c2/c3 at (row+8, col..col+1)
#pragma unroll
    for (int mi = 0; mi < 2; mi++) {
#pragma unroll
        for (int ni = 0; ni < 4; ni++) {
            int colL = n0w + ni*8 + tig*2;          // within 64-wide tile
            float2 bv = make_float2(0.f, 0.f);
            if (MODE >= 1) {
                bv.x = bias[n0 + colL];
                bv.y = bias[n0 + colL + 1];
            }
#pragma unroll
            for (int rh = 0; rh < 2; rh++) {
                int rr = r0 + m0 + mi*16 + gid + rh*8;
                float2 o;
                o.x = acc[mi][ni][rh*2+0] + bv.x;
                o.y = acc[mi][ni][rh*2+1] + bv.y;
                if (MODE == 2) {
                    o.x = fmaxf(o.x, 0.f); o.y = fmaxf(o.y, 0.f);
                }
                if (HEADOUT) {
                    int bb = rr >> 8, t = rr & 255;
                    size_t oi = (((size_t)bb*H_ + blockIdx.z)*T_ + t)*64 + colL;
                    *(float2*)(C + oi) = o;
                } else {
                    size_t ci = (size_t)rr*M + n0 + colL;
                    if (MODE == 3) {
                        float2 rv = *(const float2*)(res + ci);
                        o.x += rv.x; o.y += rv.y;
                    }
                    *(float2*)(C + ci) = o;
                }
            }
        }
    }
}

// ---------------- causal flash attention -----------------------------------
__global__ __launch_bounds__(256)
void attn_kernel(const float* __restrict__ q, const float* __restrict__ k,
                 const float* __restrict__ v, float* __restrict__ o) {
    extern __shared__ float sm[];
    float* Qs  = sm;            // [64][68] transposed: Qs[d][r]
    float* KPs = sm + 64*68;    // Ks[d][c], reused as Ps[r][c]
    float* Vs  = sm + 2*64*68;  // Vs[s][d]
    const int tid = threadIdx.x;
    const int tx = tid & 15, ty = tid >> 4;
    const int bh = blockIdx.y;
    const int q0 = blockIdx.x * 64;
    const float* qb = q + (size_t)bh*T_*64;
    const float* kb = k + (size_t)bh*T_*64;
    const float* vb = v + (size_t)bh*T_*64;

#pragma unroll
    for (int i = 0; i < 16; i++) {
        int e = tid + 256*i;
        int r = e >> 6, d = e & 63;
        Qs[d*68 + r] = qb[(q0+r)*64 + d];
    }

    const float NEG = -1e30f;
    float m[4], lse[4], acc[4][4];
#pragma unroll
    for (int i = 0; i < 4; i++) {
        m[i] = NEG; lse[i] = 0.f;
#pragma unroll
        for (int j = 0; j < 4; j++) acc[i][j] = 0.f;
    }
    const float scale = 0.125f;

    for (int s0 = 0; s0 <= q0; s0 += 64) {
        __syncthreads();
#pragma unroll
        for (int i = 0; i < 16; i++) {
            int e = tid + 256*i;
            int r = e >> 6, d = e & 63;
            KPs[d*68 + r] = kb[(s0+r)*64 + d];
            Vs [r*68 + d] = vb[(s0+r)*64 + d];
        }
        __syncthreads();

        float s[4][4];
#pragma unroll
        for (int i = 0; i < 4; i++)
#pragma unroll
            for (int j = 0; j < 4; j++) s[i][j] = 0.f;
#pragma unroll 16
        for (int d = 0; d < 64; d++) {
            float4 a = *(float4*)&Qs [d*68 + ty*4];
            float4 b = *(float4*)&KPs[d*68 + tx*4];
            float ar[4] = {a.x,a.y,a.z,a.w};
            float br[4] = {b.x,b.y,b.z,b.w};
#pragma unroll
            for (int i = 0; i < 4; i++)
#pragma unroll
                for (int j = 0; j < 4; j++)
                    s[i][j] += ar[i]*br[j];
        }

#pragma unroll
        for (int i = 0; i < 4; i++) {
            int row = q0 + ty*4 + i;
            float tm = NEG;
#pragma unroll
            for (int j = 0; j < 4; j++) {
                int col = s0 + tx*4 + j;
                float val = (col <= row) ? s[i][j]*scale : NEG;
                s[i][j] = val;
                tm = fmaxf(tm, val);
            }
            tm = fmaxf(tm, __shfl_xor_sync(0xffffffffu, tm, 1));
            tm = fmaxf(tm, __shfl_xor_sync(0xffffffffu, tm, 2));
            tm = fmaxf(tm, __shfl_xor_sync(0xffffffffu, tm, 4));
            tm = fmaxf(tm, __shfl_xor_sync(0xffffffffu, tm, 8));
            float nm = fmaxf(m[i], tm);
            float corr = __expf(m[i] - nm);
            m[i] = nm;
            float rs = 0.f;
#pragma unroll
            for (int j = 0; j < 4; j++) {
                float p = __expf(s[i][j] - nm);
                s[i][j] = p;
                rs += p;
            }
            rs += __shfl_xor_sync(0xffffffffu, rs, 1);
            rs += __shfl_xor_sync(0xffffffffu, rs, 2);
            rs += __shfl_xor_sync(0xffffffffu, rs, 4);
            rs += __shfl_xor_sync(0xffffffffu, rs, 8);
            lse[i] = lse[i]*corr + rs;
#pragma unroll
            for (int j = 0; j < 4; j++) acc[i][j] *= corr;
        }

        __syncthreads();
#pragma unroll
        for (int i = 0; i < 4; i++)
            *(float4*)&KPs[(ty*4+i)*68 + tx*4] =
                make_float4(s[i][0], s[i][1], s[i][2], s[i][3]);
        __syncthreads();

#pragma unroll 16
        for (int sI = 0; sI < 64; sI++) {
            float4 vv = *(float4*)&Vs[sI*68 + tx*4];
            float vr[4] = {vv.x,vv.y,vv.z,vv.w};
            float pr[4];
#pragma unroll
            for (int i = 0; i < 4; i++) pr[i] = KPs[(ty*4+i)*68 + sI];
#pragma unroll
            for (int i = 0; i < 4; i++)
#pragma unroll
                for (int j = 0; j < 4; j++)
                    acc[i][j] += pr[i]*vr[j];
        }
    }

    int bb = bh / H_, h = bh % H_;
#pragma unroll
    for (int i = 0; i < 4; i++) {
        float inv = 1.f / lse[i];
        int t = q0 + ty*4 + i;
        size_t oi = ((size_t)bb*T_ + t)*D_ + h*64 + tx*4;
        *(float4*)(o + oi) = make_float4(acc[i][0]*inv, acc[i][1]*inv,
                                         acc[i][2]*inv, acc[i][3]*inv);
    }
}

// ---------------- launch ----------------------------------------------------
extern "C" void kernel_launch(void* const* d_in, const int* in_sizes, int n_in,
                              void* d_out, int out_size) {
    const int*   idx   = (const int*)  d_in[0];
    const float* tok   = (const float*)d_in[1];
    const float* pos   = (const float*)d_in[2];
    const float* Wq    = (const float*)d_in[3];
    const float* Wk    = (const float*)d_in[4];
    const float* Wv    = (const float*)d_in[5];
    const float* Wproj = (const float*)d_in[6];
    const float* bproj = (const float*)d_in[7];
    const float* ln1g  = (const float*)d_in[8];
    const float* ln1b  = (const float*)d_in[9];
    const float* ln2g  = (const float*)d_in[10];
    const float* ln2b  = (const float*)d_in[11];
    const float* W1    = (const float*)d_in[12];
    const float* b1    = (const float*)d_in[13];
    const float* W2    = (const float*)d_in[14];
    const float* b2    = (const float*)d_in[15];
    const float* lnfg  = (const float*)d_in[16];
    const float* lnfb  = (const float*)d_in[17];
    const float* Wlm   = (const float*)d_in[18];
    const float* blm   = (const float*)d_in[19];
    float* out = (float*)d_out;

    float *x, *xn, *q, *k, *v, *o, *h;
    cudaGetSymbolAddress((void**)&x,  g_x);
    cudaGetSymbolAddress((void**)&xn, g_xn);
    cudaGetSymbolAddress((void**)&q,  g_q);
    cudaGetSymbolAddress((void**)&k,  g_k);
    cudaGetSymbolAddress((void**)&v,  g_v);
    cudaGetSymbolAddress((void**)&o,  g_o);
    cudaGetSymbolAddress((void**)&h,  g_h);

    cudaFuncSetAttribute(attn_kernel,
        cudaFuncAttributeMaxDynamicSharedMemorySize, 3*64*68*4);

    embed_kernel<<<(N_*D_/4)/256, 256>>>(idx, tok, pos, x);

    for (int l = 0; l < L_; l++) {
        ln_kernel<<<N_/8, 256>>>(x, ln1g + l*D_, ln1b + l*D_, xn);

        dim3 gq(1, N_/128, H_);
        size_t woff = (size_t)l * H_ * D_ * HS_;
        gemm_tc<0,true><<<gq, 256>>>(xn, Wq + woff, nullptr, nullptr, q, D_, 64);
        gemm_tc<0,true><<<gq, 256>>>(xn, Wk + woff, nullptr, nullptr, k, D_, 64);
        gemm_tc<0,true><<<gq, 256>>>(xn, Wv + woff, nullptr, nullptr, v, D_, 64);

        attn_kernel<<<dim3(T_/64, B_*H_), 256, 3*64*68*4>>>(q, k, v, o);

        gemm_tc<3,false><<<dim3(D_/64, N_/128), 256>>>(
            o, Wproj + (size_t)l*D_*D_, bproj + l*D_, x, x, D_, D_);

        ln_kernel<<<N_/8, 256>>>(x, ln2g + l*D_, ln2b + l*D_, xn);

        gemm_tc<2,false><<<dim3(FF_/64, N_/128), 256>>>(
            xn, W1 + (size_t)l*D_*FF_, b1 + l*FF_, nullptr, h, D_, FF_);

        gemm_tc<3,false><<<dim3(D_/64, N_/128), 256>>>(
            h, W2 + (size_t)l*FF_*D_, b2 + l*D_, x, x, FF_, D_);
    }

    ln_kernel<<<N_/8, 256>>>(x, lnfg, lnfb, xn);
    gemm_tc<1,false><<<dim3(V_/64, N_/128), 256>>>(
        xn, Wlm, blm, nullptr, out, D_, V_);
}

// round 8
// speedup vs baseline: 1.6752x; 1.1179x over previous
#include <cuda_runtime.h>
#include <cstdint>
#include <math.h>

#define B_ 256
#define T_ 256
#define V_ 128
#define D_ 384
#define H_ 6
#define HS_ 64
#define L_ 6
#define FF_ 1536
#define N_ (B_*T_)   // 65536 tokens

// ---------------- scratch ---------------------------------------------------
__device__ float g_x [N_*D_];
__device__ float g_xn[N_*D_];
__device__ float g_q [N_*D_];
__device__ float g_k [N_*D_];
__device__ float g_v [N_*D_];
__device__ float g_o [N_*D_];
__device__ float g_h [N_*FF_];

// packed tf32-rounded weights
#define WQKV_OFF  0
#define WQKV_SZ   (L_*D_*3*D_)            // 6*384*1152 = 2,654,208
#define WPROJ_OFF (WQKV_OFF + WQKV_SZ)
#define WPROJ_SZ  (L_*D_*D_)              // 884,736
#define W1_OFF    (WPROJ_OFF + WPROJ_SZ)
#define W1_SZ     (L_*D_*FF_)             // 3,538,944
#define W2_OFF    (W1_OFF + W1_SZ)
#define W2_SZ     (L_*FF_*D_)             // 3,538,944
#define WLM_OFF   (W2_OFF + W2_SZ)
#define WLM_SZ    (D_*V_)                 // 49,152
#define WTOT      (WLM_OFF + WLM_SZ)
__device__ float g_w[WTOT];

// ---------------- tf32 helpers ---------------------------------------------
__device__ __forceinline__ uint32_t f2tf32(float f) {
    uint32_t r;
    asm("cvt.rna.tf32.f32 %0, %1;" : "=r"(r) : "f"(f));
    return r;
}
__device__ __forceinline__ float rndtf(float f) {
    return __uint_as_float(f2tf32(f));
}
__device__ __forceinline__ void mma_tf32(float c[4], const uint32_t a[4],
                                         const uint32_t b[2]) {
    asm volatile(
        "mma.sync.aligned.m16n8k8.row.col.f32.tf32.tf32.f32 "
        "{%0,%1,%2,%3}, {%4,%5,%6,%7}, {%8,%9}, {%0,%1,%2,%3};"
        : "+f"(c[0]), "+f"(c[1]), "+f"(c[2]), "+f"(c[3])
        : "r"(a[0]), "r"(a[1]), "r"(a[2]), "r"(a[3]),
          "r"(b[0]), "r"(b[1]));
}
__device__ __forceinline__ void cpasync16(uint32_t smem, const void* g) {
    asm volatile("cp.async.cg.shared.global [%0], [%1], 16;"
                 :: "r"(smem), "l"(g));
}
__device__ __forceinline__ uint32_t smaddr(const void* p) {
    return (uint32_t)__cvta_generic_to_shared(p);
}

// ---------------- weight pre-pack -------------------------------------------
__global__ void pack_qkv_kernel(const float* __restrict__ Wq,
                                const float* __restrict__ Wk,
                                const float* __restrict__ Wv,
                                float* __restrict__ dst) {
    int i = blockIdx.x * 256 + threadIdx.x;          // over L*D*1152
    int n  = i % (3*D_);
    int ld = i / (3*D_);
    int d  = ld % D_, l = ld / D_;
    int qkv = n / D_;
    int rem = n - qkv*D_;
    int h = rem >> 6, hs = rem & 63;
    const float* W = (qkv == 0) ? Wq : (qkv == 1 ? Wk : Wv);
    float v = W[(((size_t)l*H_ + h)*D_ + d)*HS_ + hs];
    dst[i] = rndtf(v);
}

__global__ void round_copy_kernel(const float* __restrict__ src,
                                  float* __restrict__ dst) {
    int i = blockIdx.x * 256 + threadIdx.x;
    dst[i] = rndtf(src[i]);
}

// ---------------- embedding ------------------------------------------------
__global__ void embed_kernel(const int* __restrict__ idx,
                             const float* __restrict__ tok,
                             const float* __restrict__ pos,
                             float* __restrict__ x) {
    int i = blockIdx.x * 256 + threadIdx.x;
    int n = i / (D_/4);
    int dq = i % (D_/4);
    int t = n & (T_-1);
    int id = idx[n];
    float4 a = ((const float4*)tok)[id * (D_/4) + dq];
    float4 p = ((const float4*)pos)[t  * (D_/4) + dq];
    float4 r;
    r.x = a.x + p.x; r.y = a.y + p.y; r.z = a.z + p.z; r.w = a.w + p.w;
    ((float4*)x)[i] = r;
}

// ---------------- layernorm (warp per row, tf32-rounded output) -------------
__global__ void ln_kernel(const float* __restrict__ x,
                          const float* __restrict__ g,
                          const float* __restrict__ b,
                          float* __restrict__ out) {
    int row  = blockIdx.x * 8 + (threadIdx.x >> 5);
    int lane = threadIdx.x & 31;
    const float* xr = x + (size_t)row * D_;
    float vals[12];
    float s = 0.f, s2 = 0.f;
#pragma unroll
    for (int i = 0; i < 12; i++) {
        float t = xr[lane + 32*i];
        vals[i] = t; s += t; s2 += t*t;
    }
#pragma unroll
    for (int off = 16; off; off >>= 1) {
        s  += __shfl_xor_sync(0xffffffffu, s,  off);
        s2 += __shfl_xor_sync(0xffffffffu, s2, off);
    }
    float mean = s * (1.f/D_);
    float var  = s2 * (1.f/D_) - mean*mean;
    float rstd = rsqrtf(var + 1e-5f);
    float* orow = out + (size_t)row * D_;
#pragma unroll
    for (int i = 0; i < 12; i++) {
        int d = lane + 32*i;
        orow[d] = rndtf((vals[i] - mean) * rstd * g[d] + b[d]);
    }
}

// ---------------- pipelined TF32 GEMM ---------------------------------------
// C[N x M] = A[N x K] @ B[K x M] (+epilogue). A,B already tf32-rounded.
// CTA tile 128x64, BK=32, 2-stage cp.async. 8 warps, each 32x32.
// Smem: A [128][36] row-major (stride 36), B [32][72] row-major (stride 72).
// MODE: 0 none(QKV scatter), 1 +bias, 2 relu(+bias)+round, 3 +bias+residual
#define A_STG (128*36)
#define B_STG (32*72)
#define GEMM_SMEM ((2*A_STG + 2*B_STG)*4)

__device__ __forceinline__ void fill_stage(float* As, float* Bs,
        const float* A, const float* Bp, int r0, int n0, int K, int ldb,
        int k0, int tid) {
#pragma unroll
    for (int i = 0; i < 4; i++) {          // A tile: 1024 float4 / 256 thr
        int f = i*256 + tid;
        int m = f >> 3, c4 = f & 7;
        cpasync16(smaddr(As + m*36 + c4*4),
                  A + (size_t)(r0+m)*K + k0 + c4*4);
    }
#pragma unroll
    for (int i = 0; i < 2; i++) {          // B tile: 512 float4 / 256 thr
        int f = i*256 + tid;
        int kk = f >> 4, c4 = f & 15;
        cpasync16(smaddr(Bs + kk*72 + c4*4),
                  Bp + (size_t)(k0+kk)*ldb + n0 + c4*4);
    }
}

template<int MODE, bool QKV>
__global__ __launch_bounds__(256)
void gemm2(const float* __restrict__ A, const float* __restrict__ Bp,
           const float* __restrict__ bias, const float* __restrict__ res,
           float* __restrict__ C0, float* __restrict__ C1,
           float* __restrict__ C2, int K, int M) {
    extern __shared__ float sm[];
    float* As = sm;                 // 2 stages
    float* Bs = sm + 2*A_STG;

    const int tid  = threadIdx.x;
    const int lane = tid & 31, warp = tid >> 5;
    const int gid  = lane >> 2, tig = lane & 3;
    const int wm   = warp >> 1, wn = warp & 1;
    const int m0   = wm * 32,   n0w = wn * 32;
    const int r0   = blockIdx.y * 128;
    const int n0   = blockIdx.x * 64;

    float acc[2][4][4];
#pragma unroll
    for (int i = 0; i < 2; i++)
#pragma unroll
        for (int j = 0; j < 4; j++)
#pragma unroll
            for (int c = 0; c < 4; c++) acc[i][j][c] = 0.f;

    fill_stage(As, Bs, A, Bp, r0, n0, K, M, 0, tid);
    asm volatile("cp.async.commit_group;");

    int s = 0;
    for (int k0 = 0; k0 < K; k0 += 32) {
        if (k0 + 32 < K) {
            fill_stage(As + (1-s)*A_STG, Bs + (1-s)*B_STG,
                       A, Bp, r0, n0, K, M, k0 + 32, tid);
            asm volatile("cp.async.commit_group;");
            asm volatile("cp.async.wait_group 1;");
        } else {
            asm volatile("cp.async.wait_group 0;");
        }
        __syncthreads();

        const float* Ab = As + s*A_STG;
        const float* Bb = Bs + s*B_STG;
#pragma unroll
        for (int ks = 0; ks < 4; ks++) {
            const int kb = ks * 8;
            uint32_t af[2][4], bf[4][2];
#pragma unroll
            for (int mi = 0; mi < 2; mi++) {
                int rb = m0 + mi*16 + gid;
                af[mi][0] = __float_as_uint(Ab[(rb    )*36 + kb + tig    ]);
                af[mi][1] = __float_as_uint(Ab[(rb + 8)*36 + kb + tig    ]);
                af[mi][2] = __float_as_uint(Ab[(rb    )*36 + kb + tig + 4]);
                af[mi][3] = __float_as_uint(Ab[(rb + 8)*36 + kb + tig + 4]);
            }
#pragma unroll
            for (int ni = 0; ni < 4; ni++) {
                int cb = n0w + ni*8 + gid;
                bf[ni][0] = __float_as_uint(Bb[(kb + tig    )*72 + cb]);
                bf[ni][1] = __float_as_uint(Bb[(kb + tig + 4)*72 + cb]);
            }
#pragma unroll
            for (int mi = 0; mi < 2; mi++)
#pragma unroll
                for (int ni = 0; ni < 4; ni++)
                    mma_tf32(acc[mi][ni], af[mi], bf[ni]);
        }
        __syncthreads();
        s ^= 1;
    }

    // ---- epilogue ----
    if (QKV) {
        int nt = blockIdx.x;                 // 0..17
        int qkv = nt / H_, h = nt - qkv*H_;
        float* Cd = (qkv == 0) ? C0 : (qkv == 1 ? C1 : C2);
#pragma unroll
        for (int mi = 0; mi < 2; mi++) {
#pragma unroll
            for (int ni = 0; ni < 4; ni++) {
                int colL = n0w + ni*8 + tig*2;
#pragma unroll
                for (int rh = 0; rh < 2; rh++) {
                    int rr = r0 + m0 + mi*16 + gid + rh*8;
                    int bb = rr >> 8, t = rr & 255;
                    size_t oi = (((size_t)bb*H_ + h)*T_ + t)*64 + colL;
                    *(float2*)(Cd + oi) =
                        make_float2(acc[mi][ni][rh*2+0], acc[mi][ni][rh*2+1]);
                }
            }
        }
    } else {
#pragma unroll
        for (int mi = 0; mi < 2; mi++) {
#pragma unroll
            for (int ni = 0; ni < 4; ni++) {
                int colL = n0w + ni*8 + tig*2;
                float2 bv = make_float2(0.f, 0.f);
                if (MODE >= 1) {
                    bv.x = bias[n0 + colL];
                    bv.y = bias[n0 + colL + 1];
                }
#pragma unroll
                for (int rh = 0; rh < 2; rh++) {
                    int rr = r0 + m0 + mi*16 + gid + rh*8;
                    float2 o;
                    o.x = acc[mi][ni][rh*2+0] + bv.x;
                    o.y = acc[mi][ni][rh*2+1] + bv.y;
                    if (MODE == 2) {
                        o.x = rndtf(fmaxf(o.x, 0.f));
                        o.y = rndtf(fmaxf(o.y, 0.f));
                    }
                    size_t ci = (size_t)rr*M + n0 + colL;
                    if (MODE == 3) {
                        float2 rv = *(const float2*)(res + ci);
                        o.x += rv.x; o.y += rv.y;
                    }
                    *(float2*)(C0 + ci) = o;
                }
            }
        }
    }
}

// ---------------- causal flash attention (fp32, tf32-rounded out) -----------
__global__ __launch_bounds__(256)
void attn_kernel(const float* __restrict__ q, const float* __restrict__ k,
                 const float* __restrict__ v, float* __restrict__ o) {
    extern __shared__ float sm[];
    float* Qs  = sm;
    float* KPs = sm + 64*68;
    float* Vs  = sm + 2*64*68;
    const int tid = threadIdx.x;
    const int tx = tid & 15, ty = tid >> 4;
    const int bh = blockIdx.y;
    const int q0 = blockIdx.x * 64;
    const float* qb = q + (size_t)bh*T_*64;
    const float* kb = k + (size_t)bh*T_*64;
    const float* vb = v + (size_t)bh*T_*64;

#pragma unroll
    for (int i = 0; i < 16; i++) {
        int e = tid + 256*i;
        int r = e >> 6, d = e & 63;
        Qs[d*68 + r] = qb[(q0+r)*64 + d];
    }

    const float NEG = -1e30f;
    float m[4], lse[4], acc[4][4];
#pragma unroll
    for (int i = 0; i < 4; i++) {
        m[i] = NEG; lse[i] = 0.f;
#pragma unroll
        for (int j = 0; j < 4; j++) acc[i][j] = 0.f;
    }
    const float scale = 0.125f;

    for (int s0 = 0; s0 <= q0; s0 += 64) {
        __syncthreads();
#pragma unroll
        for (int i = 0; i < 16; i++) {
            int e = tid + 256*i;
            int r = e >> 6, d = e & 63;
            KPs[d*68 + r] = kb[(s0+r)*64 + d];
            Vs [r*68 + d] = vb[(s0+r)*64 + d];
        }
        __syncthreads();

        float s[4][4];
#pragma unroll
        for (int i = 0; i < 4; i++)
#pragma unroll
            for (int j = 0; j < 4; j++) s[i][j] = 0.f;
#pragma unroll 16
        for (int d = 0; d < 64; d++) {
            float4 a = *(float4*)&Qs [d*68 + ty*4];
            float4 b = *(float4*)&KPs[d*68 + tx*4];
            float ar[4] = {a.x,a.y,a.z,a.w};
            float br[4] = {b.x,b.y,b.z,b.w};
#pragma unroll
            for (int i = 0; i < 4; i++)
#pragma unroll
                for (int j = 0; j < 4; j++)
                    s[i][j] += ar[i]*br[j];
        }

#pragma unroll
        for (int i = 0; i < 4; i++) {
            int row = q0 + ty*4 + i;
            float tm = NEG;
#pragma unroll
            for (int j = 0; j < 4; j++) {
                int col = s0 + tx*4 + j;
                float val = (col <= row) ? s[i][j]*scale : NEG;
                s[i][j] = val;
                tm = fmaxf(tm, val);
            }
            tm = fmaxf(tm, __shfl_xor_sync(0xffffffffu, tm, 1));
            tm = fmaxf(tm, __shfl_xor_sync(0xffffffffu, tm, 2));
            tm = fmaxf(tm, __shfl_xor_sync(0xffffffffu, tm, 4));
            tm = fmaxf(tm, __shfl_xor_sync(0xffffffffu, tm, 8));
            float nm = fmaxf(m[i], tm);
            float corr = __expf(m[i] - nm);
            m[i] = nm;
            float rs = 0.f;
#pragma unroll
            for (int j = 0; j < 4; j++) {
                float p = __expf(s[i][j] - nm);
                s[i][j] = p;
                rs += p;
            }
            rs += __shfl_xor_sync(0xffffffffu, rs, 1);
            rs += __shfl_xor_sync(0xffffffffu, rs, 2);
            rs += __shfl_xor_sync(0xffffffffu, rs, 4);
            rs += __shfl_xor_sync(0xffffffffu, rs, 8);
            lse[i] = lse[i]*corr + rs;
#pragma unroll
            for (int j = 0; j < 4; j++) acc[i][j] *= corr;
        }

        __syncthreads();
#pragma unroll
        for (int i = 0; i < 4; i++)
            *(float4*)&KPs[(ty*4+i)*68 + tx*4] =
                make_float4(s[i][0], s[i][1], s[i][2], s[i][3]);
        __syncthreads();

#pragma unroll 16
        for (int sI = 0; sI < 64; sI++) {
            float4 vv = *(float4*)&Vs[sI*68 + tx*4];
            float vr[4] = {vv.x,vv.y,vv.z,vv.w};
            float pr[4];
#pragma unroll
            for (int i = 0; i < 4; i++) pr[i] = KPs[(ty*4+i)*68 + sI];
#pragma unroll
            for (int i = 0; i < 4; i++)
#pragma unroll
                for (int j = 0; j < 4; j++)
                    acc[i][j] += pr[i]*vr[j];
        }
    }

    int bb = bh / H_, h = bh % H_;
#pragma unroll
    for (int i = 0; i < 4; i++) {
        float inv = 1.f / lse[i];
        int t = q0 + ty*4 + i;
        size_t oi = ((size_t)bb*T_ + t)*D_ + h*64 + tx*4;
        *(float4*)(o + oi) = make_float4(rndtf(acc[i][0]*inv),
                                         rndtf(acc[i][1]*inv),
                                         rndtf(acc[i][2]*inv),
                                         rndtf(acc[i][3]*inv));
    }
}

// ---------------- launch ----------------------------------------------------
extern "C" void kernel_launch(void* const* d_in, const int* in_sizes, int n_in,
                              void* d_out, int out_size) {
    const int*   idx   = (const int*)  d_in[0];
    const float* tok   = (const float*)d_in[1];
    const float* pos   = (const float*)d_in[2];
    const float* Wq    = (const float*)d_in[3];
    const float* Wk    = (const float*)d_in[4];
    const float* Wv    = (const float*)d_in[5];
    const float* Wproj = (const float*)d_in[6];
    const float* bproj = (const float*)d_in[7];
    const float* ln1g  = (const float*)d_in[8];
    const float* ln1b  = (const float*)d_in[9];
    const float* ln2g  = (const float*)d_in[10];
    const float* ln2b  = (const float*)d_in[11];
    const float* W1    = (const float*)d_in[12];
    const float* b1    = (const float*)d_in[13];
    const float* W2    = (const float*)d_in[14];
    const float* b2    = (const float*)d_in[15];
    const float* lnfg  = (const float*)d_in[16];
    const float* lnfb  = (const float*)d_in[17];
    const float* Wlm   = (const float*)d_in[18];
    const float* blm   = (const float*)d_in[19];
    float* out = (float*)d_out;

    float *x, *xn, *q, *k, *v, *o, *h, *w;
    cudaGetSymbolAddress((void**)&x,  g_x);
    cudaGetSymbolAddress((void**)&xn, g_xn);
    cudaGetSymbolAddress((void**)&q,  g_q);
    cudaGetSymbolAddress((void**)&k,  g_k);
    cudaGetSymbolAddress((void**)&v,  g_v);
    cudaGetSymbolAddress((void**)&o,  g_o);
    cudaGetSymbolAddress((void**)&h,  g_h);
    cudaGetSymbolAddress((void**)&w,  g_w);

    cudaFuncSetAttribute(attn_kernel,
        cudaFuncAttributeMaxDynamicSharedMemorySize, 3*64*68*4);
    cudaFuncSetAttribute(gemm2<0,true>,
        cudaFuncAttributeMaxDynamicSharedMemorySize, GEMM_SMEM);
    cudaFuncSetAttribute(gemm2<1,false>,
        cudaFuncAttributeMaxDynamicSharedMemorySize, GEMM_SMEM);
    cudaFuncSetAttribute(gemm2<2,false>,
        cudaFuncAttributeMaxDynamicSharedMemorySize, GEMM_SMEM);
    cudaFuncSetAttribute(gemm2<3,false>,
        cudaFuncAttributeMaxDynamicSharedMemorySize, GEMM_SMEM);

    // weight pre-pack (tf32-rounded)
    pack_qkv_kernel<<<WQKV_SZ/256, 256>>>(Wq, Wk, Wv, w + WQKV_OFF);
    round_copy_kernel<<<WPROJ_SZ/256, 256>>>(Wproj, w + WPROJ_OFF);
    round_copy_kernel<<<W1_SZ/256, 256>>>(W1, w + W1_OFF);
    round_copy_kernel<<<W2_SZ/256, 256>>>(W2, w + W2_OFF);
    round_copy_kernel<<<WLM_SZ/256, 256>>>(Wlm, w + WLM_OFF);

    embed_kernel<<<(N_*D_/4)/256, 256>>>(idx, tok, pos, x);

    for (int l = 0; l < L_; l++) {
        ln_kernel<<<N_/8, 256>>>(x, ln1g + l*D_, ln1b + l*D_, xn);

        gemm2<0,true><<<dim3(3*D_/64, N_/128), 256, GEMM_SMEM>>>(
            xn, w + WQKV_OFF + (size_t)l*D_*3*D_, nullptr, nullptr,
            q, k, v, D_, 3*D_);

        attn_kernel<<<dim3(T_/64, B_*H_), 256, 3*64*68*4>>>(q, k, v, o);

        gemm2<3,false><<<dim3(D_/64, N_/128), 256, GEMM_SMEM>>>(
            o, w + WPROJ_OFF + (size_t)l*D_*D_, bproj + l*D_, x,
            x, nullptr, nullptr, D_, D_);

        ln_kernel<<<N_/8, 256>>>(x, ln2g + l*D_, ln2b + l*D_, xn);

        gemm2<2,false><<<dim3(FF_/64, N_/128), 256, GEMM_SMEM>>>(
            xn, w + W1_OFF + (size_t)l*D_*FF_, b1 + l*FF_, nullptr,
            h, nullptr, nullptr, D_, FF_);

        gemm2<3,false><<<dim3(D_/64, N_/128), 256, GEMM_SMEM>>>(
            h, w + W2_OFF + (size_t)l*FF_*D_, b2 + l*D_, x,
            x, nullptr, nullptr, FF_, D_);
    }

    ln_kernel<<<N_/8, 256>>>(x, lnfg, lnfb, xn);
    gemm2<1,false><<<dim3(V_/64, N_/128), 256, GEMM_SMEM>>>(
        xn, w + WLM_OFF, blm, nullptr, out, nullptr, nullptr, D_, V_);
}

// round 9
// speedup vs baseline: 2.4958x; 1.4898x over previous
#include <cuda_runtime.h>
#include <cstdint>
#include <math.h>

#define B_ 256
#define T_ 256
#define V_ 128
#define D_ 384
#define H_ 6
#define HS_ 64
#define L_ 6
#define FF_ 1536
#define N_ (B_*T_)   // 65536 tokens

// ---------------- scratch ---------------------------------------------------
__device__ float g_x [N_*D_];
__device__ float g_xn[N_*D_];
__device__ float g_q [N_*D_];
__device__ float g_k [N_*D_];
__device__ float g_v [N_*D_];
__device__ float g_o [N_*D_];
__device__ float g_h [N_*FF_];

// packed tf32-rounded weights
#define WQKV_OFF  0
#define WQKV_SZ   (L_*D_*3*D_)
#define WPROJ_OFF (WQKV_OFF + WQKV_SZ)
#define WPROJ_SZ  (L_*D_*D_)
#define W1_OFF    (WPROJ_OFF + WPROJ_SZ)
#define W1_SZ     (L_*D_*FF_)
#define W2_OFF    (W1_OFF + W1_SZ)
#define W2_SZ     (L_*FF_*D_)
#define WLM_OFF   (W2_OFF + W2_SZ)
#define WLM_SZ    (D_*V_)
#define WTOT      (WLM_OFF + WLM_SZ)
__device__ float g_w[WTOT];

// ---------------- tf32 helpers ---------------------------------------------
__device__ __forceinline__ uint32_t f2tf32(float f) {
    uint32_t r;
    asm("cvt.rna.tf32.f32 %0, %1;" : "=r"(r) : "f"(f));
    return r;
}
__device__ __forceinline__ float rndtf(float f) {
    return __uint_as_float(f2tf32(f));
}
__device__ __forceinline__ void mma_tf32(float c[4], const uint32_t a[4],
                                         const uint32_t b[2]) {
    asm volatile(
        "mma.sync.aligned.m16n8k8.row.col.f32.tf32.tf32.f32 "
        "{%0,%1,%2,%3}, {%4,%5,%6,%7}, {%8,%9}, {%0,%1,%2,%3};"
        : "+f"(c[0]), "+f"(c[1]), "+f"(c[2]), "+f"(c[3])
        : "r"(a[0]), "r"(a[1]), "r"(a[2]), "r"(a[3]),
          "r"(b[0]), "r"(b[1]));
}
__device__ __forceinline__ void cpasync16(uint32_t smem, const void* g) {
    asm volatile("cp.async.cg.shared.global [%0], [%1], 16;"
                 :: "r"(smem), "l"(g));
}
__device__ __forceinline__ uint32_t smaddr(const void* p) {
    return (uint32_t)__cvta_generic_to_shared(p);
}

// ---------------- weight pre-pack -------------------------------------------
__global__ void pack_qkv_kernel(const float* __restrict__ Wq,
                                const float* __restrict__ Wk,
                                const float* __restrict__ Wv,
                                float* __restrict__ dst) {
    int i = blockIdx.x * 256 + threadIdx.x;          // over L*D*1152
    int n  = i % (3*D_);
    int ld = i / (3*D_);
    int d  = ld % D_, l = ld / D_;
    int qkv = n / D_;
    int rem = n - qkv*D_;
    int h = rem >> 6, hs = rem & 63;
    const float* W = (qkv == 0) ? Wq : (qkv == 1 ? Wk : Wv);
    float v = W[(((size_t)l*H_ + h)*D_ + d)*HS_ + hs];
    dst[i] = rndtf(v);
}

__global__ void round_copy_kernel(const float* __restrict__ src,
                                  float* __restrict__ dst) {
    int i = blockIdx.x * 256 + threadIdx.x;
    dst[i] = rndtf(src[i]);
}

// ---------------- embedding ------------------------------------------------
__global__ void embed_kernel(const int* __restrict__ idx,
                             const float* __restrict__ tok,
                             const float* __restrict__ pos,
                             float* __restrict__ x) {
    int i = blockIdx.x * 256 + threadIdx.x;
    int n = i / (D_/4);
    int dq = i % (D_/4);
    int t = n & (T_-1);
    int id = idx[n];
    float4 a = ((const float4*)tok)[id * (D_/4) + dq];
    float4 p = ((const float4*)pos)[t  * (D_/4) + dq];
    float4 r;
    r.x = a.x + p.x; r.y = a.y + p.y; r.z = a.z + p.z; r.w = a.w + p.w;
    ((float4*)x)[i] = r;
}

// ---------------- layernorm (warp per row, tf32-rounded output) -------------
__global__ void ln_kernel(const float* __restrict__ x,
                          const float* __restrict__ g,
                          const float* __restrict__ b,
                          float* __restrict__ out) {
    int row  = blockIdx.x * 8 + (threadIdx.x >> 5);
    int lane = threadIdx.x & 31;
    const float* xr = x + (size_t)row * D_;
    float vals[12];
    float s = 0.f, s2 = 0.f;
#pragma unroll
    for (int i = 0; i < 12; i++) {
        float t = xr[lane + 32*i];
        vals[i] = t; s += t; s2 += t*t;
    }
#pragma unroll
    for (int off = 16; off; off >>= 1) {
        s  += __shfl_xor_sync(0xffffffffu, s,  off);
        s2 += __shfl_xor_sync(0xffffffffu, s2, off);
    }
    float mean = s * (1.f/D_);
    float var  = s2 * (1.f/D_) - mean*mean;
    float rstd = rsqrtf(var + 1e-5f);
    float* orow = out + (size_t)row * D_;
#pragma unroll
    for (int i = 0; i < 12; i++) {
        int d = lane + 32*i;
        orow[d] = rndtf((vals[i] - mean) * rstd * g[d] + b[d]);
    }
}

// ---------------- pipelined TF32 GEMM, CTA 128x128 ---------------------------
// C[N x M] = A[N x K] @ B[K x M] (+epilogue). A,B already tf32-rounded.
// 8 warps, warp tile 64x32 (warp grid 2x4). BK=32, 2-stage cp.async.
// Smem: A [128][36] ([m][k]), B [32][132] ([k][n]).
// MODE: 0 none(QKV scatter), 1 +bias, 2 relu(+bias)+round, 3 +bias+residual
#define A_STG (128*36)
#define B_STG (32*132)
#define GEMM_SMEM ((2*A_STG + 2*B_STG)*4)

__device__ __forceinline__ void fill_stage(float* As, float* Bs,
        const float* A, const float* Bp, int r0, int n0, int K, int ldb,
        int k0, int tid) {
#pragma unroll
    for (int i = 0; i < 4; i++) {          // A tile: 128x32 = 1024 f4 / 256 thr
        int f = i*256 + tid;
        int m = f >> 3, c4 = f & 7;
        cpasync16(smaddr(As + m*36 + c4*4),
                  A + (size_t)(r0+m)*K + k0 + c4*4);
    }
#pragma unroll
    for (int i = 0; i < 4; i++) {          // B tile: 32x128 = 1024 f4 / 256 thr
        int f = i*256 + tid;
        int kk = f >> 5, c4 = f & 31;
        cpasync16(smaddr(Bs + kk*132 + c4*4),
                  Bp + (size_t)(k0+kk)*ldb + n0 + c4*4);
    }
}

template<int MODE, bool QKV>
__global__ __launch_bounds__(256)
void gemm3(const float* __restrict__ A, const float* __restrict__ Bp,
           const float* __restrict__ bias, const float* __restrict__ res,
           float* __restrict__ C0, float* __restrict__ C1,
           float* __restrict__ C2, int K, int M) {
    extern __shared__ float sm[];
    float* As = sm;                 // 2 stages
    float* Bs = sm + 2*A_STG;

    const int tid  = threadIdx.x;
    const int lane = tid & 31, warp = tid >> 5;
    const int gid  = lane >> 2, tig = lane & 3;
    const int wm   = warp >> 2, wn = warp & 3;     // 2 x 4 warp grid
    const int m0   = wm * 64,   n0w = wn * 32;
    const int r0   = blockIdx.y * 128;
    const int n0   = blockIdx.x * 128;

    float acc[4][4][4];
#pragma unroll
    for (int i = 0; i < 4; i++)
#pragma unroll
        for (int j = 0; j < 4; j++)
#pragma unroll
            for (int c = 0; c < 4; c++) acc[i][j][c] = 0.f;

    fill_stage(As, Bs, A, Bp, r0, n0, K, M, 0, tid);
    asm volatile("cp.async.commit_group;");

    int s = 0;
    for (int k0 = 0; k0 < K; k0 += 32) {
        if (k0 + 32 < K) {
            fill_stage(As + (1-s)*A_STG, Bs + (1-s)*B_STG,
                       A, Bp, r0, n0, K, M, k0 + 32, tid);
            asm volatile("cp.async.commit_group;");
            asm volatile("cp.async.wait_group 1;");
        } else {
            asm volatile("cp.async.wait_group 0;");
        }
        __syncthreads();

        const float* Ab = As + s*A_STG;
        const float* Bb = Bs + s*B_STG;
#pragma unroll
        for (int ks = 0; ks < 4; ks++) {
            const int kb = ks * 8;
            uint32_t af[4][4], bf[4][2];
#pragma unroll
            for (int mi = 0; mi < 4; mi++) {
                int rb = m0 + mi*16 + gid;
                af[mi][0] = __float_as_uint(Ab[(rb    )*36 + kb + tig    ]);
                af[mi][1] = __float_as_uint(Ab[(rb + 8)*36 + kb + tig    ]);
                af[mi][2] = __float_as_uint(Ab[(rb    )*36 + kb + tig + 4]);
                af[mi][3] = __float_as_uint(Ab[(rb + 8)*36 + kb + tig + 4]);
            }
#pragma unroll
            for (int ni = 0; ni < 4; ni++) {
                int cb = n0w + ni*8 + gid;
                bf[ni][0] = __float_as_uint(Bb[(kb + tig    )*132 + cb]);
                bf[ni][1] = __float_as_uint(Bb[(kb + tig + 4)*132 + cb]);
            }
#pragma unroll
            for (int mi = 0; mi < 4; mi++)
#pragma unroll
                for (int ni = 0; ni < 4; ni++)
                    mma_tf32(acc[mi][ni], af[mi], bf[ni]);
        }
        __syncthreads();
        s ^= 1;
    }

    // ---- epilogue ----
    if (QKV) {
        // each 128-col block lies wholly inside one of Q/K/V (384 = 3*128)
        int qkv = blockIdx.x / 3;
        int cbase = blockIdx.x * 128 - qkv * 384;
        float* Cd = (qkv == 0) ? C0 : (qkv == 1 ? C1 : C2);
#pragma unroll
        for (int mi = 0; mi < 4; mi++) {
#pragma unroll
            for (int ni = 0; ni < 4; ni++) {
                int c = cbase + n0w + ni*8 + tig*2;
                int h = c >> 6, hs = c & 63;
#pragma unroll
                for (int rh = 0; rh < 2; rh++) {
                    int rr = r0 + m0 + mi*16 + gid + rh*8;
                    int bb = rr >> 8, t = rr & 255;
                    size_t oi = (((size_t)bb*H_ + h)*T_ + t)*64 + hs;
                    *(float2*)(Cd + oi) =
                        make_float2(acc[mi][ni][rh*2+0], acc[mi][ni][rh*2+1]);
                }
            }
        }
    } else {
#pragma unroll
        for (int mi = 0; mi < 4; mi++) {
#pragma unroll
            for (int ni = 0; ni < 4; ni++) {
                int col = n0 + n0w + ni*8 + tig*2;
                float2 bv = make_float2(0.f, 0.f);
                if (MODE >= 1) {
                    bv.x = bias[col];
                    bv.y = bias[col + 1];
                }
#pragma unroll
                for (int rh = 0; rh < 2; rh++) {
                    int rr = r0 + m0 + mi*16 + gid + rh*8;
                    float2 o;
                    o.x = acc[mi][ni][rh*2+0] + bv.x;
                    o.y = acc[mi][ni][rh*2+1] + bv.y;
                    if (MODE == 2) {
                        o.x = rndtf(fmaxf(o.x, 0.f));
                        o.y = rndtf(fmaxf(o.y, 0.f));
                    }
                    size_t ci = (size_t)rr*M + col;
                    if (MODE == 3) {
                        float2 rv = *(const float2*)(res + ci);
                        o.x += rv.x; o.y += rv.y;
                    }
                    *(float2*)(C0 + ci) = o;
                }
            }
        }
    }
}

// ---------------- causal flash attention (fp32, tf32-rounded out) -----------
__global__ __launch_bounds__(256)
void attn_kernel(const float* __restrict__ q, const float* __restrict__ k,
                 const float* __restrict__ v, float* __restrict__ o) {
    extern __shared__ float sm[];
    float* Qs  = sm;
    float* KPs = sm + 64*68;
    float* Vs  = sm + 2*64*68;
    const int tid = threadIdx.x;
    const int tx = tid & 15, ty = tid >> 4;
    const int bh = blockIdx.y;
    const int q0 = blockIdx.x * 64;
    const float* qb = q + (size_t)bh*T_*64;
    const float* kb = k + (size_t)bh*T_*64;
    const float* vb = v + (size_t)bh*T_*64;

#pragma unroll
    for (int i = 0; i < 16; i++) {
        int e = tid + 256*i;
        int r = e >> 6, d = e & 63;
        Qs[d*68 + r] = qb[(q0+r)*64 + d];
    }

    const float NEG = -1e30f;
    float m[4], lse[4], acc[4][4];
#pragma unroll
    for (int i = 0; i < 4; i++) {
        m[i] = NEG; lse[i] = 0.f;
#pragma unroll
        for (int j = 0; j < 4; j++) acc[i][j] = 0.f;
    }
    const float scale = 0.125f;

    for (int s0 = 0; s0 <= q0; s0 += 64) {
        __syncthreads();
#pragma unroll
        for (int i = 0; i < 16; i++) {
            int e = tid + 256*i;
            int r = e >> 6, d = e & 63;
            KPs[d*68 + r] = kb[(s0+r)*64 + d];
            Vs [r*68 + d] = vb[(s0+r)*64 + d];
        }
        __syncthreads();

        float s[4][4];
#pragma unroll
        for (int i = 0; i < 4; i++)
#pragma unroll
            for (int j = 0; j < 4; j++) s[i][j] = 0.f;
#pragma unroll 16
        for (int d = 0; d < 64; d++) {
            float4 a = *(float4*)&Qs [d*68 + ty*4];
            float4 b = *(float4*)&KPs[d*68 + tx*4];
            float ar[4] = {a.x,a.y,a.z,a.w};
            float br[4] = {b.x,b.y,b.z,b.w};
#pragma unroll
            for (int i = 0; i < 4; i++)
#pragma unroll
                for (int j = 0; j < 4; j++)
                    s[i][j] += ar[i]*br[j];
        }

#pragma unroll
        for (int i = 0; i < 4; i++) {
            int row = q0 + ty*4 + i;
            float tm = NEG;
#pragma unroll
            for (int j = 0; j < 4; j++) {
                int col = s0 + tx*4 + j;
                float val = (col <= row) ? s[i][j]*scale : NEG;
                s[i][j] = val;
                tm = fmaxf(tm, val);
            }
            tm = fmaxf(tm, __shfl_xor_sync(0xffffffffu, tm, 1));
            tm = fmaxf(tm, __shfl_xor_sync(0xffffffffu, tm, 2));
            tm = fmaxf(tm, __shfl_xor_sync(0xffffffffu, tm, 4));
            tm = fmaxf(tm, __shfl_xor_sync(0xffffffffu, tm, 8));
            float nm = fmaxf(m[i], tm);
            float corr = __expf(m[i] - nm);
            m[i] = nm;
            float rs = 0.f;
#pragma unroll
            for (int j = 0; j < 4; j++) {
                float p = __expf(s[i][j] - nm);
                s[i][j] = p;
                rs += p;
            }
            rs += __shfl_xor_sync(0xffffffffu, rs, 1);
            rs += __shfl_xor_sync(0xffffffffu, rs, 2);
            rs += __shfl_xor_sync(0xffffffffu, rs, 4);
            rs += __shfl_xor_sync(0xffffffffu, rs, 8);
            lse[i] = lse[i]*corr + rs;
#pragma unroll
            for (int j = 0; j < 4; j++) acc[i][j] *= corr;
        }

        __syncthreads();
#pragma unroll
        for (int i = 0; i < 4; i++)
            *(float4*)&KPs[(ty*4+i)*68 + tx*4] =
                make_float4(s[i][0], s[i][1], s[i][2], s[i][3]);
        __syncthreads();

#pragma unroll 16
        for (int sI = 0; sI < 64; sI++) {
            float4 vv = *(float4*)&Vs[sI*68 + tx*4];
            float vr[4] = {vv.x,vv.y,vv.z,vv.w};
            float pr[4];
#pragma unroll
            for (int i = 0; i < 4; i++) pr[i] = KPs[(ty*4+i)*68 + sI];
#pragma unroll
            for (int i = 0; i < 4; i++)
#pragma unroll
                for (int j = 0; j < 4; j++)
                    acc[i][j] += pr[i]*vr[j];
        }
    }

    int bb = bh / H_, h = bh % H_;
#pragma unroll
    for (int i = 0; i < 4; i++) {
        float inv = 1.f / lse[i];
        int t = q0 + ty*4 + i;
        size_t oi = ((size_t)bb*T_ + t)*D_ + h*64 + tx*4;
        *(float4*)(o + oi) = make_float4(rndtf(acc[i][0]*inv),
                                         rndtf(acc[i][1]*inv),
                                         rndtf(acc[i][2]*inv),
                                         rndtf(acc[i][3]*inv));
    }
}

// ---------------- launch ----------------------------------------------------
extern "C" void kernel_launch(void* const* d_in, const int* in_sizes, int n_in,
                              void* d_out, int out_size) {
    const int*   idx   = (const int*)  d_in[0];
    const float* tok   = (const float*)d_in[1];
    const float* pos   = (const float*)d_in[2];
    const float* Wq    = (const float*)d_in[3];
    const float* Wk    = (const float*)d_in[4];
    const float* Wv    = (const float*)d_in[5];
    const float* Wproj = (const float*)d_in[6];
    const float* bproj = (const float*)d_in[7];
    const float* ln1g  = (const float*)d_in[8];
    const float* ln1b  = (const float*)d_in[9];
    const float* ln2g  = (const float*)d_in[10];
    const float* ln2b  = (const float*)d_in[11];
    const float* W1    = (const float*)d_in[12];
    const float* b1    = (const float*)d_in[13];
    const float* W2    = (const float*)d_in[14];
    const float* b2    = (const float*)d_in[15];
    const float* lnfg  = (const float*)d_in[16];
    const float* lnfb  = (const float*)d_in[17];
    const float* Wlm   = (const float*)d_in[18];
    const float* blm   = (const float*)d_in[19];
    float* out = (float*)d_out;

    float *x, *xn, *q, *k, *v, *o, *h, *w;
    cudaGetSymbolAddress((void**)&x,  g_x);
    cudaGetSymbolAddress((void**)&xn, g_xn);
    cudaGetSymbolAddress((void**)&q,  g_q);
    cudaGetSymbolAddress((void**)&k,  g_k);
    cudaGetSymbolAddress((void**)&v,  g_v);
    cudaGetSymbolAddress((void**)&o,  g_o);
    cudaGetSymbolAddress((void**)&h,  g_h);
    cudaGetSymbolAddress((void**)&w,  g_w);

    cudaFuncSetAttribute(attn_kernel,
        cudaFuncAttributeMaxDynamicSharedMemorySize, 3*64*68*4);
    cudaFuncSetAttribute(gemm3<0,true>,
        cudaFuncAttributeMaxDynamicSharedMemorySize, GEMM_SMEM);
    cudaFuncSetAttribute(gemm3<1,false>,
        cudaFuncAttributeMaxDynamicSharedMemorySize, GEMM_SMEM);
    cudaFuncSetAttribute(gemm3<2,false>,
        cudaFuncAttributeMaxDynamicSharedMemorySize, GEMM_SMEM);
    cudaFuncSetAttribute(gemm3<3,false>,
        cudaFuncAttributeMaxDynamicSharedMemorySize, GEMM_SMEM);

    // weight pre-pack (tf32-rounded)
    pack_qkv_kernel<<<WQKV_SZ/256, 256>>>(Wq, Wk, Wv, w + WQKV_OFF);
    round_copy_kernel<<<WPROJ_SZ/256, 256>>>(Wproj, w + WPROJ_OFF);
    round_copy_kernel<<<W1_SZ/256, 256>>>(W1, w + W1_OFF);
    round_copy_kernel<<<W2_SZ/256, 256>>>(W2, w + W2_OFF);
    round_copy_kernel<<<WLM_SZ/256, 256>>>(Wlm, w + WLM_OFF);

    embed_kernel<<<(N_*D_/4)/256, 256>>>(idx, tok, pos, x);

    for (int l = 0; l < L_; l++) {
        ln_kernel<<<N_/8, 256>>>(x, ln1g + l*D_, ln1b + l*D_, xn);

        gemm3<0,true><<<dim3(9, N_/128), 256, GEMM_SMEM>>>(
            xn, w + WQKV_OFF + (size_t)l*D_*3*D_, nullptr, nullptr,
            q, k, v, D_, 3*D_);

        attn_kernel<<<dim3(T_/64, B_*H_), 256, 3*64*68*4>>>(q, k, v, o);

        gemm3<3,false><<<dim3(3, N_/128), 256, GEMM_SMEM>>>(
            o, w + WPROJ_OFF + (size_t)l*D_*D_, bproj + l*D_, x,
            x, nullptr, nullptr, D_, D_);

        ln_kernel<<<N_/8, 256>>>(x, ln2g + l*D_, ln2b + l*D_, xn);

        gemm3<2,false><<<dim3(12, N_/128), 256, GEMM_SMEM>>>(
            xn, w + W1_OFF + (size_t)l*D_*FF_, b1 + l*FF_, nullptr,
            h, nullptr, nullptr, D_, FF_);

        gemm3<3,false><<<dim3(3, N_/128), 256, GEMM_SMEM>>>(
            h, w + W2_OFF + (size_t)l*FF_*D_, b2 + l*D_, x,
            x, nullptr, nullptr, FF_, D_);
    }

    ln_kernel<<<N_/8, 256>>>(x, lnfg, lnfb, xn);
    gemm3<1,false><<<dim3(1, N_/128), 256, GEMM_SMEM>>>(
        xn, w + WLM_OFF, blm, nullptr, out, nullptr, nullptr, D_, V_);
}